// round 10
// baseline (speedup 1.0000x reference)
#include <cuda_runtime.h>
#include <cuda_bf16.h>
#include <math.h>
#include <stdint.h>

// Problem constants
#define Bn  2
#define Tn  2048
#define Cn  1024
#define Hn  16
#define HDn 64
#define QKV_N (3*Cn)          // 3072
#define Mrows (Bn*Tn)         // 4096

// Scratch (allocation-free: __device__ globals)
__device__ float g_qkv[(size_t)Mrows * QKV_N];
__device__ __nv_bfloat16 g_xhi[(size_t)Mrows * Cn];
__device__ __nv_bfloat16 g_xlo[(size_t)Mrows * Cn];
__device__ __nv_bfloat16 g_wahi[(size_t)Cn * QKV_N];
__device__ __nv_bfloat16 g_walo[(size_t)Cn * QKV_N];
__device__ __nv_bfloat16 g_wphi[(size_t)Cn * Cn];
__device__ __nv_bfloat16 g_wplo[(size_t)Cn * Cn];
__device__ __nv_bfloat16 g_yhi[(size_t)Mrows * Cn];
__device__ __nv_bfloat16 g_ylo[(size_t)Mrows * Cn];

// ===========================================================================
// fp32 -> bf16 hi/lo split (elementwise, vectorized)
// ===========================================================================
__global__ __launch_bounds__(256)
void split_kernel(const float* __restrict__ src, __nv_bfloat16* __restrict__ hi,
                  __nv_bfloat16* __restrict__ lo, int n4)
{
    int i = blockIdx.x * blockDim.x + threadIdx.x;
    if (i >= n4) return;
    float4 v = ((const float4*)src)[i];
    __nv_bfloat16 hx = __float2bfloat16(v.x), hy = __float2bfloat16(v.y);
    __nv_bfloat16 hz = __float2bfloat16(v.z), hw = __float2bfloat16(v.w);
    ((__nv_bfloat162*)hi)[2 * i]     = __nv_bfloat162(hx, hy);
    ((__nv_bfloat162*)hi)[2 * i + 1] = __nv_bfloat162(hz, hw);
    ((__nv_bfloat162*)lo)[2 * i] = __nv_bfloat162(
        __float2bfloat16(v.x - __bfloat162float(hx)),
        __float2bfloat16(v.y - __bfloat162float(hy)));
    ((__nv_bfloat162*)lo)[2 * i + 1] = __nv_bfloat162(
        __float2bfloat16(v.z - __bfloat162float(hz)),
        __float2bfloat16(v.w - __bfloat162float(hw)));
}

// ===========================================================================
// Pipelined bf16 split GEMM (known-good): C = (Ahi+Alo)@(Bhi+Blo)+bias
// ===========================================================================
#define GBM 128
#define GBN 128
#define GBK 32
#define ASTR 40
#define BSTR 136
#define OFF_AHI 0
#define OFF_ALO 10240
#define OFF_BHI 20480
#define OFF_BLO 29184
#define STAGE_BYTES 37888
#define GEMM_SMEM (2*STAGE_BYTES)

__device__ __forceinline__ void cpasync16(uint32_t dst, const void* src) {
    asm volatile("cp.async.cg.shared.global [%0], [%1], 16;" :: "r"(dst), "l"(src));
}
__device__ __forceinline__ void ldsm4(uint32_t r[4], uint32_t addr) {
    asm volatile("ldmatrix.sync.aligned.m8n8.x4.shared.b16 {%0,%1,%2,%3}, [%4];"
                 : "=r"(r[0]), "=r"(r[1]), "=r"(r[2]), "=r"(r[3]) : "r"(addr));
}
__device__ __forceinline__ void ldsm4t(uint32_t r[4], uint32_t addr) {
    asm volatile("ldmatrix.sync.aligned.m8n8.x4.trans.shared.b16 {%0,%1,%2,%3}, [%4];"
                 : "=r"(r[0]), "=r"(r[1]), "=r"(r[2]), "=r"(r[3]) : "r"(addr));
}
__device__ __forceinline__ void mma_bf16(float d[4], const uint32_t a[4],
                                         uint32_t b0, uint32_t b1) {
    asm volatile(
        "mma.sync.aligned.m16n8k16.row.col.f32.bf16.bf16.f32 "
        "{%0,%1,%2,%3}, {%4,%5,%6,%7}, {%8,%9}, {%0,%1,%2,%3};"
        : "+f"(d[0]), "+f"(d[1]), "+f"(d[2]), "+f"(d[3])
        : "r"(a[0]), "r"(a[1]), "r"(a[2]), "r"(a[3]), "r"(b0), "r"(b1));
}

__global__ __launch_bounds__(256, 2)
void bgemm_split(const __nv_bfloat16* __restrict__ Ahi_g, const __nv_bfloat16* __restrict__ Alo_g,
                 const __nv_bfloat16* __restrict__ Bhi_g, const __nv_bfloat16* __restrict__ Blo_g,
                 const float* __restrict__ bias, float* __restrict__ C,
                 int M, int N, int K)
{
    extern __shared__ char gsm[];
    const int tid  = threadIdx.x;
    const int warp = tid >> 5;
    const int lane = tid & 31;
    const int g  = lane >> 2;
    const int tg = lane & 3;

    const int bm = blockIdx.y * GBM;
    const int bn = blockIdx.x * GBN;
    const int warp_m = (warp >> 1) * 32;
    const int warp_n = (warp & 1) * 64;

    const int ar = tid >> 2, ac = (tid & 3) * 8;
    const int br = tid >> 4, bc = (tid & 15) * 8;
    const __nv_bfloat16* aih = Ahi_g + (size_t)(bm + ar) * K + ac;
    const __nv_bfloat16* ail = Alo_g + (size_t)(bm + ar) * K + ac;
    const __nv_bfloat16* bih = Bhi_g + (size_t)br * N + bn + bc;
    const __nv_bfloat16* bil = Blo_g + (size_t)br * N + bn + bc;
    const size_t a64 = (size_t)64 * K;
    const size_t b16 = (size_t)16 * N;

    const uint32_t smb = (uint32_t)__cvta_generic_to_shared(gsm);
    const uint32_t dA  = (uint32_t)(ar * ASTR + ac) * 2;
    const uint32_t dA2 = (uint32_t)((ar + 64) * ASTR + ac) * 2;
    const uint32_t dB  = (uint32_t)(br * BSTR + bc) * 2;
    const uint32_t dB2 = (uint32_t)((br + 16) * BSTR + bc) * 2;

    float acc[2][8][4];
    #pragma unroll
    for (int mt = 0; mt < 2; mt++)
        #pragma unroll
        for (int nt = 0; nt < 8; nt++)
            #pragma unroll
            for (int i = 0; i < 4; i++) acc[mt][nt][i] = 0.f;

    const int NK = K / GBK;

    #define ISSUE_STAGE(s, kit) do {                                         \
        uint32_t so = smb + (uint32_t)(s) * STAGE_BYTES;                     \
        size_t ka = (size_t)(kit) * GBK;                                     \
        size_t kb = (size_t)(kit) * GBK * (size_t)N;                         \
        cpasync16(so + OFF_AHI + dA,  aih + ka);                             \
        cpasync16(so + OFF_AHI + dA2, aih + a64 + ka);                       \
        cpasync16(so + OFF_ALO + dA,  ail + ka);                             \
        cpasync16(so + OFF_ALO + dA2, ail + a64 + ka);                       \
        cpasync16(so + OFF_BHI + dB,  bih + kb);                             \
        cpasync16(so + OFF_BHI + dB2, bih + b16 + kb);                       \
        cpasync16(so + OFF_BLO + dB,  bil + kb);                             \
        cpasync16(so + OFF_BLO + dB2, bil + b16 + kb);                       \
        asm volatile("cp.async.commit_group;");                              \
    } while (0)

    ISSUE_STAGE(0, 0);

    const int a_r = lane & 15;
    const int a_c = (lane >> 4) * 8;

    for (int it = 0; it < NK; it++) {
        if (it + 1 < NK) {
            ISSUE_STAGE((it + 1) & 1, it + 1);
            asm volatile("cp.async.wait_group 1;");
        } else {
            asm volatile("cp.async.wait_group 0;");
        }
        __syncthreads();

        const uint32_t sb = smb + (uint32_t)(it & 1) * STAGE_BYTES;
        #pragma unroll
        for (int ks = 0; ks < 2; ks++) {
            const int kk = ks * 16;
            uint32_t ah[2][4], al[2][4];
            #pragma unroll
            for (int mt = 0; mt < 2; mt++) {
                uint32_t off = (uint32_t)((warp_m + mt * 16 + a_r) * ASTR + kk + a_c) * 2;
                ldsm4(ah[mt], sb + OFF_AHI + off);
                ldsm4(al[mt], sb + OFF_ALO + off);
            }
            #pragma unroll
            for (int np = 0; np < 4; np++) {
                uint32_t bh[4], bl[4];
                uint32_t off = (uint32_t)((kk + a_r) * BSTR + warp_n + np * 16 + a_c) * 2;
                ldsm4t(bh, sb + OFF_BHI + off);
                ldsm4t(bl, sb + OFF_BLO + off);
                #pragma unroll
                for (int pass = 0; pass < 3; pass++) {
                    #pragma unroll
                    for (int half = 0; half < 2; half++) {
                        const int nt = np * 2 + half;
                        const uint32_t b0 = (pass == 1) ? bl[half * 2]     : bh[half * 2];
                        const uint32_t b1 = (pass == 1) ? bl[half * 2 + 1] : bh[half * 2 + 1];
                        #pragma unroll
                        for (int mt = 0; mt < 2; mt++) {
                            mma_bf16(acc[mt][nt], (pass == 2) ? al[mt] : ah[mt], b0, b1);
                        }
                    }
                }
            }
        }
        __syncthreads();
    }

    #pragma unroll
    for (int nt = 0; nt < 8; nt++) {
        const int col = bn + warp_n + nt * 8 + 2 * tg;
        const float2 bs = *(const float2*)&bias[col];
        #pragma unroll
        for (int mt = 0; mt < 2; mt++) {
            const int row0 = bm + warp_m + mt * 16 + g;
            float2 o0 = make_float2(acc[mt][nt][0] + bs.x, acc[mt][nt][1] + bs.y);
            float2 o1 = make_float2(acc[mt][nt][2] + bs.x, acc[mt][nt][3] + bs.y);
            *(float2*)&C[(size_t)row0 * N + col]       = o0;
            *(float2*)&C[(size_t)(row0 + 8) * N + col] = o1;
        }
    }
    #undef ISSUE_STAGE
}

// ===========================================================================
// Flash attention v3: QK tf32 (RNA at point of use), PV bf16-split.
// Software-pipelined staging: K raw fp32 via cp.async (double buffer),
// V via registers (convert mid-compute). ONE __syncthreads per KV tile.
// ===========================================================================
#define AT_BQ   128
#define AT_BKV  64
#define KSTR    68                       // K raw stride (fp32 words)
#define KBUF_W  (AT_BKV * KSTR)          // 4352 words per K buffer
#define VSTR    72                       // V pair-row stride (uint32 words)
#define VBUF_W  (2 * 32 * VSTR)          // 4608 words per V buffer (hi+lo)
#define AT_SMEM ((2 * KBUF_W + 2 * VBUF_W) * 4)   // 71680 bytes
#define SCALE   0.125f

__device__ __forceinline__ float tf32r(float x) {
    uint32_t u;
    asm("cvt.rna.tf32.f32 %0, %1;" : "=r"(u) : "f"(x));
    return __uint_as_float(u);
}
__device__ __forceinline__ void mma_tf32(float d[4], const uint32_t a[4],
                                         uint32_t b0, uint32_t b1) {
    asm volatile(
        "mma.sync.aligned.m16n8k8.row.col.f32.tf32.tf32.f32 "
        "{%0,%1,%2,%3}, {%4,%5,%6,%7}, {%8,%9}, {%0,%1,%2,%3};"
        : "+f"(d[0]), "+f"(d[1]), "+f"(d[2]), "+f"(d[3])
        : "r"(a[0]), "r"(a[1]), "r"(a[2]), "r"(a[3]), "r"(b0), "r"(b1));
}

__global__ __launch_bounds__(256)
void attn_tc(const float* __restrict__ qkv,
             __nv_bfloat16* __restrict__ yhi, __nv_bfloat16* __restrict__ ylo)
{
    extern __shared__ float pool[];   // [K0 | K1 | V0(hi,lo) | V1(hi,lo)]

    const int b = blockIdx.z, h = blockIdx.y;
    const int qtile = gridDim.x - 1 - blockIdx.x;   // heavy tiles first
    const int q0 = qtile * AT_BQ;
    const int tid  = threadIdx.x;
    const int warp = tid >> 5;
    const int lane = tid & 31;
    const int g  = lane >> 2;
    const int tg = lane & 3;

    const int qi0 = q0 + warp * 16 + g;
    const int qi1 = qi0 + 8;
    const int w_qmax = q0 + warp * 16 + 15;
    const int w_qmin = q0 + warp * 16;

    // ---- prologue: stage Q (pre-scaled, RNA tf32) into pool, extract A-frags
    {
        const float* qg = qkv + ((size_t)(b * Tn + q0)) * QKV_N + h * HDn;
        #pragma unroll
        for (int itr = 0; itr < 8; itr++) {
            int f = itr * 256 + tid;
            int r = f >> 4, c = (f & 15) << 2;
            float4 v = *(const float4*)(qg + (size_t)r * QKV_N + c);
            float4 t;
            t.x = tf32r(v.x * SCALE); t.y = tf32r(v.y * SCALE);
            t.z = tf32r(v.z * SCALE); t.w = tf32r(v.w * SCALE);
            *(float4*)&pool[r * KSTR + c] = t;
        }
    }
    __syncthreads();

    uint32_t Aq[8][4];
    {
        const int r0 = warp * 16 + g;
        #pragma unroll
        for (int k = 0; k < 8; k++) {
            Aq[k][0] = __float_as_uint(pool[(r0    ) * KSTR + k * 8 + tg    ]);
            Aq[k][1] = __float_as_uint(pool[(r0 + 8) * KSTR + k * 8 + tg    ]);
            Aq[k][2] = __float_as_uint(pool[(r0    ) * KSTR + k * 8 + tg + 4]);
            Aq[k][3] = __float_as_uint(pool[(r0 + 8) * KSTR + k * 8 + tg + 4]);
        }
    }
    __syncthreads();

    // per-thread staging geometry
    const uint32_t smb = (uint32_t)__cvta_generic_to_shared(pool);
    int krow[4]; uint32_t kdst[4];
    #pragma unroll
    for (int i = 0; i < 4; i++) {
        int f = i * 256 + tid;
        krow[i] = f >> 4;
        kdst[i] = (uint32_t)(krow[i] * KSTR + (f & 15) * 4) * 4;
    }
    const float* kbase = qkv + (size_t)b * Tn * QKV_N +     Cn + h * HDn;
    const float* vbase = qkv + (size_t)b * Tn * QKV_N + 2 * Cn + h * HDn;

    const int NT = (q0 + AT_BQ) / AT_BKV;   // >= 2

    #define K_ISSUE(tile, s) do {                                             \
        const uint32_t _so = smb + (uint32_t)(s) * (KBUF_W * 4);              \
        const int _kt = (tile) * AT_BKV;                                      \
        _Pragma("unroll")                                                     \
        for (int _i = 0; _i < 4; _i++) {                                      \
            cpasync16(_so + kdst[_i],                                         \
                      kbase + (size_t)(_kt + krow[_i]) * QKV_N                \
                            + ((kdst[_i] >> 2) % KSTR));                      \
        }                                                                     \
        asm volatile("cp.async.commit_group;");                               \
    } while (0)

    #define V_LDG(tile, vr) do {                                              \
        const float* _vg = vbase + (size_t)((tile) * AT_BKV) * QKV_N;         \
        _Pragma("unroll")                                                     \
        for (int _itr = 0; _itr < 2; _itr++) {                                \
            int _f = _itr * 256 + tid;                                        \
            int _p = _f >> 4, _c4 = (_f & 15) * 4;                            \
            const float* _r0 = _vg + (size_t)(2 * _p) * QKV_N + _c4;          \
            vr[2 * _itr]     = *(const float4*)_r0;                           \
            vr[2 * _itr + 1] = *(const float4*)(_r0 + QKV_N);                 \
        }                                                                     \
    } while (0)

    #define V_STS(s, vr) do {                                                 \
        uint32_t* _Vph = (uint32_t*)(pool + 2 * KBUF_W + (s) * VBUF_W);       \
        uint32_t* _Vpl = _Vph + 32 * VSTR;                                    \
        _Pragma("unroll")                                                     \
        for (int _itr = 0; _itr < 2; _itr++) {                                \
            int _f = _itr * 256 + tid;                                        \
            int _p = _f >> 4, _c4 = (_f & 15) * 4;                            \
            float4 _v0 = vr[2 * _itr], _v1 = vr[2 * _itr + 1];                \
            const float _e0[4] = {_v0.x, _v0.y, _v0.z, _v0.w};                \
            const float _e1[4] = {_v1.x, _v1.y, _v1.z, _v1.w};                \
            uint32_t _hw[4], _lw[4];                                          \
            _Pragma("unroll")                                                 \
            for (int _j = 0; _j < 4; _j++) {                                  \
                __nv_bfloat162 _hp = __floats2bfloat162_rn(_e0[_j], _e1[_j]); \
                _hw[_j] = *(uint32_t*)&_hp;                                   \
                float2 _hf = __bfloat1622float2(_hp);                         \
                __nv_bfloat162 _lp = __floats2bfloat162_rn(_e0[_j] - _hf.x,   \
                                                           _e1[_j] - _hf.y); \
                _lw[_j] = *(uint32_t*)&_lp;                                   \
            }                                                                 \
            *(uint4*)&_Vph[_p * VSTR + _c4] =                                 \
                make_uint4(_hw[0], _hw[1], _hw[2], _hw[3]);                   \
            *(uint4*)&_Vpl[_p * VSTR + _c4] =                                 \
                make_uint4(_lw[0], _lw[1], _lw[2], _lw[3]);                   \
        }                                                                     \
    } while (0)

    float4 vr[4];
    // stage tile 0
    K_ISSUE(0, 0);
    V_LDG(0, vr);
    asm volatile("cp.async.wait_group 0;");
    __syncthreads();            // K0 visible
    V_STS(0, vr);
    __syncthreads();            // V0 visible

    float O[8][4];
    #pragma unroll
    for (int nt = 0; nt < 8; nt++)
        #pragma unroll
        for (int i = 0; i < 4; i++) O[nt][i] = 0.f;

    float m0 = -INFINITY, m1 = -INFINITY;
    float l0 = 0.f, l1 = 0.f;

    for (int t = 0; t < NT; t++) {
        const int kt = t * AT_BKV;
        const bool more = (t + 1 < NT);
        if (more) {
            K_ISSUE(t + 1, (t + 1) & 1);
            V_LDG(t + 1, vr);
        }

        const float*    Kb  = pool + (t & 1) * KBUF_W;
        const uint32_t* Vph = (const uint32_t*)(pool + 2 * KBUF_W + (t & 1) * VBUF_W);
        const uint32_t* Vpl = Vph + 32 * VSTR;
        const bool active = (kt <= w_qmax);

        float S[8][4];
        if (active) {
            // ---- S = Q @ K^T (K raw fp32 in smem, RNA cvt at use) ----
            #pragma unroll
            for (int nt = 0; nt < 8; nt++) {
                S[nt][0] = S[nt][1] = S[nt][2] = S[nt][3] = 0.f;
            }
            #pragma unroll
            for (int k = 0; k < 8; k++) {
                #pragma unroll
                for (int nt = 0; nt < 8; nt++) {
                    float k0 = Kb[(nt * 8 + g) * KSTR + k * 8 + tg    ];
                    float k1 = Kb[(nt * 8 + g) * KSTR + k * 8 + tg + 4];
                    mma_tf32(S[nt], Aq[k],
                             __float_as_uint(tf32r(k0)),
                             __float_as_uint(tf32r(k1)));
                }
            }

            const bool need_mask = (kt + AT_BKV - 1 > w_qmin);
            if (need_mask) {
                #pragma unroll
                for (int nt = 0; nt < 8; nt++) {
                    int j0 = kt + nt * 8 + 2 * tg;
                    int j1 = j0 + 1;
                    if (j0 > qi0) S[nt][0] = -INFINITY;
                    if (j1 > qi0) S[nt][1] = -INFINITY;
                    if (j0 > qi1) S[nt][2] = -INFINITY;
                    if (j1 > qi1) S[nt][3] = -INFINITY;
                }
            }

            // ---- online softmax ----
            float mc0 = -INFINITY, mc1 = -INFINITY;
            #pragma unroll
            for (int nt = 0; nt < 8; nt++) {
                mc0 = fmaxf(mc0, fmaxf(S[nt][0], S[nt][1]));
                mc1 = fmaxf(mc1, fmaxf(S[nt][2], S[nt][3]));
            }
            mc0 = fmaxf(mc0, __shfl_xor_sync(0xffffffffu, mc0, 1));
            mc0 = fmaxf(mc0, __shfl_xor_sync(0xffffffffu, mc0, 2));
            mc1 = fmaxf(mc1, __shfl_xor_sync(0xffffffffu, mc1, 1));
            mc1 = fmaxf(mc1, __shfl_xor_sync(0xffffffffu, mc1, 2));

            float mn0 = fmaxf(m0, mc0);
            float mn1 = fmaxf(m1, mc1);
            float corr0 = __expf(m0 - mn0);
            float corr1 = __expf(m1 - mn1);
            m0 = mn0; m1 = mn1;

            float ps0 = 0.f, ps1 = 0.f;
            #pragma unroll
            for (int nt = 0; nt < 8; nt++) {
                S[nt][0] = __expf(S[nt][0] - mn0);
                S[nt][1] = __expf(S[nt][1] - mn0);
                S[nt][2] = __expf(S[nt][2] - mn1);
                S[nt][3] = __expf(S[nt][3] - mn1);
                ps0 += S[nt][0] + S[nt][1];
                ps1 += S[nt][2] + S[nt][3];
            }
            ps0 += __shfl_xor_sync(0xffffffffu, ps0, 1);
            ps0 += __shfl_xor_sync(0xffffffffu, ps0, 2);
            ps1 += __shfl_xor_sync(0xffffffffu, ps1, 1);
            ps1 += __shfl_xor_sync(0xffffffffu, ps1, 2);
            l0 = l0 * corr0 + ps0;
            l1 = l1 * corr1 + ps1;

            #pragma unroll
            for (int nt = 0; nt < 8; nt++) {
                O[nt][0] *= corr0; O[nt][1] *= corr0;
                O[nt][2] *= corr1; O[nt][3] *= corr1;
            }
        }

        // convert+store next V tile into the OTHER buffer (no hazard with PV)
        if (more) V_STS((t + 1) & 1, vr);

        if (active) {
            // ---- O += P @ V, bf16 split (C-frag P packs directly) ----
            #pragma unroll
            for (int s = 0; s < 4; s++) {
                uint32_t aph[4], apl[4];
                const float pv[8] = {
                    S[2*s  ][0], S[2*s  ][1], S[2*s  ][2], S[2*s  ][3],
                    S[2*s+1][0], S[2*s+1][1], S[2*s+1][2], S[2*s+1][3]
                };
                #pragma unroll
                for (int q = 0; q < 4; q++) {
                    __nv_bfloat162 hp = __floats2bfloat162_rn(pv[2*q], pv[2*q+1]);
                    aph[q] = *(uint32_t*)&hp;
                    float2 hf = __bfloat1622float2(hp);
                    __nv_bfloat162 lp = __floats2bfloat162_rn(pv[2*q] - hf.x,
                                                              pv[2*q+1] - hf.y);
                    apl[q] = *(uint32_t*)&lp;
                }
                const int pr0 = (8 * s + tg) * VSTR;
                const int pr1 = (8 * s + tg + 4) * VSTR;
                #pragma unroll
                for (int dd = 0; dd < 8; dd++) {
                    const int dc = dd * 8 + g;
                    uint32_t b0h = Vph[pr0 + dc];
                    uint32_t b1h = Vph[pr1 + dc];
                    uint32_t b0l = Vpl[pr0 + dc];
                    uint32_t b1l = Vpl[pr1 + dc];
                    mma_bf16(O[dd], aph, b0h, b1h);
                    mma_bf16(O[dd], aph, b0l, b1l);
                    mma_bf16(O[dd], apl, b0h, b1h);
                }
            }
        }

        if (more) asm volatile("cp.async.wait_group 0;");
        __syncthreads();
    }
    #undef K_ISSUE
    #undef V_LDG
    #undef V_STS

    // ---- finalize: divide by l, split to bf16 hi/lo, store ----
    const float inv0 = 1.f / l0;
    const float inv1 = 1.f / l1;
    const size_t row0 = (size_t)(b * Tn + qi0) * Cn + h * HDn;
    const size_t row1 = (size_t)(b * Tn + qi1) * Cn + h * HDn;
    #pragma unroll
    for (int nt = 0; nt < 8; nt++) {
        int c = nt * 8 + 2 * tg;
        float v00 = O[nt][0] * inv0, v01 = O[nt][1] * inv0;
        float v10 = O[nt][2] * inv1, v11 = O[nt][3] * inv1;
        __nv_bfloat16 h00 = __float2bfloat16(v00), h01 = __float2bfloat16(v01);
        __nv_bfloat16 h10 = __float2bfloat16(v10), h11 = __float2bfloat16(v11);
        *(__nv_bfloat162*)&yhi[row0 + c] = __nv_bfloat162(h00, h01);
        *(__nv_bfloat162*)&yhi[row1 + c] = __nv_bfloat162(h10, h11);
        *(__nv_bfloat162*)&ylo[row0 + c] = __nv_bfloat162(
            __float2bfloat16(v00 - __bfloat162float(h00)),
            __float2bfloat16(v01 - __bfloat162float(h01)));
        *(__nv_bfloat162*)&ylo[row1 + c] = __nv_bfloat162(
            __float2bfloat16(v10 - __bfloat162float(h10)),
            __float2bfloat16(v11 - __bfloat162float(h11)));
    }
}

// ---------------------------------------------------------------------------
// Launch
// ---------------------------------------------------------------------------
extern "C" void kernel_launch(void* const* d_in, const int* in_sizes, int n_in,
                              void* d_out, int out_size)
{
    const float* x      = (const float*)d_in[0];
    const float* w_attn = (const float*)d_in[1];
    const float* b_attn = (const float*)d_in[2];
    const float* w_proj = (const float*)d_in[3];
    const float* b_proj = (const float*)d_in[4];
    float* out = (float*)d_out;

    float* qkv_ptr; __nv_bfloat16 *xhi, *xlo, *wahi, *walo, *wphi, *wplo, *yhi, *ylo;
    cudaGetSymbolAddress((void**)&qkv_ptr, g_qkv);
    cudaGetSymbolAddress((void**)&xhi,  g_xhi);
    cudaGetSymbolAddress((void**)&xlo,  g_xlo);
    cudaGetSymbolAddress((void**)&wahi, g_wahi);
    cudaGetSymbolAddress((void**)&walo, g_walo);
    cudaGetSymbolAddress((void**)&wphi, g_wphi);
    cudaGetSymbolAddress((void**)&wplo, g_wplo);
    cudaGetSymbolAddress((void**)&yhi,  g_yhi);
    cudaGetSymbolAddress((void**)&ylo,  g_ylo);

    cudaFuncSetAttribute(bgemm_split, cudaFuncAttributeMaxDynamicSharedMemorySize, GEMM_SMEM);
    cudaFuncSetAttribute(attn_tc, cudaFuncAttributeMaxDynamicSharedMemorySize, AT_SMEM);

    // 0) split inputs into bf16 hi/lo
    {
        int n4;
        n4 = (Mrows * Cn) / 4;
        split_kernel<<<(n4 + 255) / 256, 256>>>(x, xhi, xlo, n4);
        n4 = (Cn * QKV_N) / 4;
        split_kernel<<<(n4 + 255) / 256, 256>>>(w_attn, wahi, walo, n4);
        n4 = (Cn * Cn) / 4;
        split_kernel<<<(n4 + 255) / 256, 256>>>(w_proj, wphi, wplo, n4);
    }
    // 1) QKV projection
    {
        dim3 grid(QKV_N / GBN, Mrows / GBM);
        bgemm_split<<<grid, 256, GEMM_SMEM>>>(xhi, xlo, wahi, walo, b_attn,
                                              qkv_ptr, Mrows, QKV_N, Cn);
    }
    // 2) Causal attention (pipelined tf32 QK + bf16-split PV)
    {
        dim3 grid(Tn / AT_BQ, Hn, Bn);
        attn_tc<<<grid, 256, AT_SMEM>>>(qkv_ptr, yhi, ylo);
    }
    // 3) Output projection
    {
        dim3 grid(Cn / GBN, Mrows / GBM);
        bgemm_split<<<grid, 256, GEMM_SMEM>>>(yhi, ylo, wphi, wplo, b_proj,
                                              out, Mrows, Cn, Cn);
    }
}

// round 11
// speedup vs baseline: 1.2707x; 1.2707x over previous
#include <cuda_runtime.h>
#include <cuda_bf16.h>
#include <cuda_fp16.h>
#include <math.h>
#include <stdint.h>

// Problem constants
#define Bn  2
#define Tn  2048
#define Cn  1024
#define Hn  16
#define HDn 64
#define QKV_N (3*Cn)          // 3072
#define Mrows (Bn*Tn)         // 4096

// Scratch (allocation-free: __device__ globals)
__device__ float g_qkv[(size_t)Mrows * QKV_N];
__device__ __half g_xhi[(size_t)Mrows * Cn];
__device__ __half g_xlo[(size_t)Mrows * Cn];
__device__ __half g_wah[(size_t)Cn * QKV_N];     // fp16(w_attn), unsplit
__device__ __half g_wph[(size_t)Cn * Cn];        // fp16(w_proj), unsplit
__device__ __half g_yhi[(size_t)Mrows * Cn];
__device__ __half g_ylo[(size_t)Mrows * Cn];

// ===========================================================================
// fp32 -> fp16 hi/lo split  and  fp32 -> fp16 convert (weights)
// ===========================================================================
__global__ __launch_bounds__(256)
void split2h(const float* __restrict__ src, __half* __restrict__ hi,
             __half* __restrict__ lo, int n4)
{
    int i = blockIdx.x * blockDim.x + threadIdx.x;
    if (i >= n4) return;
    float4 v = ((const float4*)src)[i];
    __half hx = __float2half_rn(v.x), hy = __float2half_rn(v.y);
    __half hz = __float2half_rn(v.z), hw = __float2half_rn(v.w);
    ((__half2*)hi)[2 * i]     = __half2(hx, hy);
    ((__half2*)hi)[2 * i + 1] = __half2(hz, hw);
    ((__half2*)lo)[2 * i] = __half2(
        __float2half_rn(v.x - __half2float(hx)),
        __float2half_rn(v.y - __half2float(hy)));
    ((__half2*)lo)[2 * i + 1] = __half2(
        __float2half_rn(v.z - __half2float(hz)),
        __float2half_rn(v.w - __half2float(hw)));
}

__global__ __launch_bounds__(256)
void conv_h(const float* __restrict__ src, __half* __restrict__ dst, int n4)
{
    int i = blockIdx.x * blockDim.x + threadIdx.x;
    if (i >= n4) return;
    float4 v = ((const float4*)src)[i];
    ((__half2*)dst)[2 * i]     = __floats2half2_rn(v.x, v.y);
    ((__half2*)dst)[2 * i + 1] = __floats2half2_rn(v.z, v.w);
}

// ===========================================================================
// Pipelined fp16 2-pass GEMM: C = (Ahi+Alo) @ Bh + bias
// A split fp16 (hi/lo), B plain fp16. Error = A*(B - fp16(B)) ~ 2.8e-4 rel.
// CTA 128x128, GBK=32, cp.async double-buffer, 8 warps (warp tile 32x64).
// ===========================================================================
#define GBM 128
#define GBN 128
#define GBK 32
#define ASTR 40
#define BSTR 136
#define OFF_AHI 0
#define OFF_ALO 10240
#define OFF_BHI 20480
#define STAGE_BYTES 29184
#define GEMM_SMEM (2*STAGE_BYTES)

__device__ __forceinline__ void cpasync16(uint32_t dst, const void* src) {
    asm volatile("cp.async.cg.shared.global [%0], [%1], 16;" :: "r"(dst), "l"(src));
}
__device__ __forceinline__ void ldsm4(uint32_t r[4], uint32_t addr) {
    asm volatile("ldmatrix.sync.aligned.m8n8.x4.shared.b16 {%0,%1,%2,%3}, [%4];"
                 : "=r"(r[0]), "=r"(r[1]), "=r"(r[2]), "=r"(r[3]) : "r"(addr));
}
__device__ __forceinline__ void ldsm4t(uint32_t r[4], uint32_t addr) {
    asm volatile("ldmatrix.sync.aligned.m8n8.x4.trans.shared.b16 {%0,%1,%2,%3}, [%4];"
                 : "=r"(r[0]), "=r"(r[1]), "=r"(r[2]), "=r"(r[3]) : "r"(addr));
}
__device__ __forceinline__ void mma_f16(float d[4], const uint32_t a[4],
                                        uint32_t b0, uint32_t b1) {
    asm volatile(
        "mma.sync.aligned.m16n8k16.row.col.f32.f16.f16.f32 "
        "{%0,%1,%2,%3}, {%4,%5,%6,%7}, {%8,%9}, {%0,%1,%2,%3};"
        : "+f"(d[0]), "+f"(d[1]), "+f"(d[2]), "+f"(d[3])
        : "r"(a[0]), "r"(a[1]), "r"(a[2]), "r"(a[3]), "r"(b0), "r"(b1));
}
__device__ __forceinline__ void mma_bf16(float d[4], const uint32_t a[4],
                                         uint32_t b0, uint32_t b1) {
    asm volatile(
        "mma.sync.aligned.m16n8k16.row.col.f32.bf16.bf16.f32 "
        "{%0,%1,%2,%3}, {%4,%5,%6,%7}, {%8,%9}, {%0,%1,%2,%3};"
        : "+f"(d[0]), "+f"(d[1]), "+f"(d[2]), "+f"(d[3])
        : "r"(a[0]), "r"(a[1]), "r"(a[2]), "r"(a[3]), "r"(b0), "r"(b1));
}

__global__ __launch_bounds__(256, 2)
void hgemm_2p(const __half* __restrict__ Ahi_g, const __half* __restrict__ Alo_g,
              const __half* __restrict__ Bh_g,
              const float* __restrict__ bias, float* __restrict__ C,
              int M, int N, int K)
{
    extern __shared__ char gsm[];
    const int tid  = threadIdx.x;
    const int warp = tid >> 5;
    const int lane = tid & 31;
    const int g  = lane >> 2;
    const int tg = lane & 3;

    const int bm = blockIdx.y * GBM;
    const int bn = blockIdx.x * GBN;
    const int warp_m = (warp >> 1) * 32;
    const int warp_n = (warp & 1) * 64;

    const int ar = tid >> 2, ac = (tid & 3) * 8;
    const int br = tid >> 4, bc = (tid & 15) * 8;
    const __half* aih = Ahi_g + (size_t)(bm + ar) * K + ac;
    const __half* ail = Alo_g + (size_t)(bm + ar) * K + ac;
    const __half* bhg = Bh_g  + (size_t)br * N + bn + bc;
    const size_t a64 = (size_t)64 * K;
    const size_t b16 = (size_t)16 * N;

    const uint32_t smb = (uint32_t)__cvta_generic_to_shared(gsm);
    const uint32_t dA  = (uint32_t)(ar * ASTR + ac) * 2;
    const uint32_t dA2 = (uint32_t)((ar + 64) * ASTR + ac) * 2;
    const uint32_t dB  = (uint32_t)(br * BSTR + bc) * 2;
    const uint32_t dB2 = (uint32_t)((br + 16) * BSTR + bc) * 2;

    float acc[2][8][4];
    #pragma unroll
    for (int mt = 0; mt < 2; mt++)
        #pragma unroll
        for (int nt = 0; nt < 8; nt++)
            #pragma unroll
            for (int i = 0; i < 4; i++) acc[mt][nt][i] = 0.f;

    const int NK = K / GBK;

    #define ISSUE_STAGE(s, kit) do {                                         \
        uint32_t so = smb + (uint32_t)(s) * STAGE_BYTES;                     \
        size_t ka = (size_t)(kit) * GBK;                                     \
        size_t kb = (size_t)(kit) * GBK * (size_t)N;                         \
        cpasync16(so + OFF_AHI + dA,  aih + ka);                             \
        cpasync16(so + OFF_AHI + dA2, aih + a64 + ka);                       \
        cpasync16(so + OFF_ALO + dA,  ail + ka);                             \
        cpasync16(so + OFF_ALO + dA2, ail + a64 + ka);                       \
        cpasync16(so + OFF_BHI + dB,  bhg + kb);                             \
        cpasync16(so + OFF_BHI + dB2, bhg + b16 + kb);                       \
        asm volatile("cp.async.commit_group;");                              \
    } while (0)

    ISSUE_STAGE(0, 0);

    const int a_r = lane & 15;
    const int a_c = (lane >> 4) * 8;

    for (int it = 0; it < NK; it++) {
        if (it + 1 < NK) {
            ISSUE_STAGE((it + 1) & 1, it + 1);
            asm volatile("cp.async.wait_group 1;");
        } else {
            asm volatile("cp.async.wait_group 0;");
        }
        __syncthreads();

        const uint32_t sb = smb + (uint32_t)(it & 1) * STAGE_BYTES;
        #pragma unroll
        for (int ks = 0; ks < 2; ks++) {
            const int kk = ks * 16;
            uint32_t ah[2][4], al[2][4];
            #pragma unroll
            for (int mt = 0; mt < 2; mt++) {
                uint32_t off = (uint32_t)((warp_m + mt * 16 + a_r) * ASTR + kk + a_c) * 2;
                ldsm4(ah[mt], sb + OFF_AHI + off);
                ldsm4(al[mt], sb + OFF_ALO + off);
            }
            #pragma unroll
            for (int np = 0; np < 4; np++) {
                uint32_t bh[4];
                uint32_t off = (uint32_t)((kk + a_r) * BSTR + warp_n + np * 16 + a_c) * 2;
                ldsm4t(bh, sb + OFF_BHI + off);
                #pragma unroll
                for (int pass = 0; pass < 2; pass++) {
                    #pragma unroll
                    for (int half = 0; half < 2; half++) {
                        const int nt = np * 2 + half;
                        #pragma unroll
                        for (int mt = 0; mt < 2; mt++) {
                            mma_f16(acc[mt][nt], pass ? al[mt] : ah[mt],
                                    bh[half * 2], bh[half * 2 + 1]);
                        }
                    }
                }
            }
        }
        __syncthreads();
    }

    #pragma unroll
    for (int nt = 0; nt < 8; nt++) {
        const int col = bn + warp_n + nt * 8 + 2 * tg;
        const float2 bs = *(const float2*)&bias[col];
        #pragma unroll
        for (int mt = 0; mt < 2; mt++) {
            const int row0 = bm + warp_m + mt * 16 + g;
            float2 o0 = make_float2(acc[mt][nt][0] + bs.x, acc[mt][nt][1] + bs.y);
            float2 o1 = make_float2(acc[mt][nt][2] + bs.x, acc[mt][nt][3] + bs.y);
            *(float2*)&C[(size_t)row0 * N + col]       = o0;
            *(float2*)&C[(size_t)(row0 + 8) * N + col] = o1;
        }
    }
    #undef ISSUE_STAGE
}

// ===========================================================================
// Flash attention (R8 known-good): QK tf32 RNA, PV bf16-split zero-shuffle.
// 256 threads (8 warps), BQ=128, KV tiles 64. Output y as fp16 hi/lo.
// ===========================================================================
#define AT_BQ   128
#define AT_BKV  64
#define KPAD    68
#define VSTR    72
#define SCALE   0.125f

__device__ __forceinline__ float tf32r(float x) {
    uint32_t u;
    asm("cvt.rna.tf32.f32 %0, %1;" : "=r"(u) : "f"(x));
    return __uint_as_float(u);
}
__device__ __forceinline__ void mma_tf32(float d[4], const uint32_t a[4],
                                         uint32_t b0, uint32_t b1) {
    asm volatile(
        "mma.sync.aligned.m16n8k8.row.col.f32.tf32.tf32.f32 "
        "{%0,%1,%2,%3}, {%4,%5,%6,%7}, {%8,%9}, {%0,%1,%2,%3};"
        : "+f"(d[0]), "+f"(d[1]), "+f"(d[2]), "+f"(d[3])
        : "r"(a[0]), "r"(a[1]), "r"(a[2]), "r"(a[3]), "r"(b0), "r"(b1));
}

__global__ __launch_bounds__(256)
void attn_tc(const float* __restrict__ qkv,
             __half* __restrict__ yhi, __half* __restrict__ ylo)
{
    __shared__ float pool[8960];
    float*    Ks  = pool;
    uint32_t* Vph = (uint32_t*)(pool + AT_BKV * KPAD);
    uint32_t* Vpl = Vph + 32 * VSTR;

    const int b = blockIdx.z, h = blockIdx.y;
    const int qtile = gridDim.x - 1 - blockIdx.x;   // heavy tiles first
    const int q0 = qtile * AT_BQ;
    const int tid  = threadIdx.x;
    const int warp = tid >> 5;
    const int lane = tid & 31;
    const int g  = lane >> 2;
    const int tg = lane & 3;

    // ---- stage Q tile (pre-scaled, tf32 RNA bits) ----
    {
        const float* qg = qkv + ((size_t)(b * Tn + q0)) * QKV_N + h * HDn;
        #pragma unroll
        for (int itr = 0; itr < 8; itr++) {
            int f = itr * 256 + tid;
            int r = f >> 4, c = (f & 15) << 2;
            float4 v = *(const float4*)(qg + (size_t)r * QKV_N + c);
            float4 t;
            t.x = tf32r(v.x * SCALE); t.y = tf32r(v.y * SCALE);
            t.z = tf32r(v.z * SCALE); t.w = tf32r(v.w * SCALE);
            *(float4*)&pool[r * KPAD + c] = t;
        }
    }
    __syncthreads();

    uint32_t Aq[8][4];
    {
        const int r0 = warp * 16 + g;
        #pragma unroll
        for (int k = 0; k < 8; k++) {
            Aq[k][0] = __float_as_uint(pool[(r0    ) * KPAD + k * 8 + tg    ]);
            Aq[k][1] = __float_as_uint(pool[(r0 + 8) * KPAD + k * 8 + tg    ]);
            Aq[k][2] = __float_as_uint(pool[(r0    ) * KPAD + k * 8 + tg + 4]);
            Aq[k][3] = __float_as_uint(pool[(r0 + 8) * KPAD + k * 8 + tg + 4]);
        }
    }
    __syncthreads();

    float O[8][4];
    #pragma unroll
    for (int nt = 0; nt < 8; nt++)
        #pragma unroll
        for (int i = 0; i < 4; i++) O[nt][i] = 0.f;

    float m0 = -INFINITY, m1 = -INFINITY;
    float l0 = 0.f, l1 = 0.f;

    const int qi0 = q0 + warp * 16 + g;
    const int qi1 = qi0 + 8;
    const int w_qmax = q0 + warp * 16 + 15;
    const int w_qmin = q0 + warp * 16;

    for (int kt = 0; kt < q0 + AT_BQ; kt += AT_BKV) {
        // ---- stage K (tf32 RNA) ----
        {
            const float* kg = qkv + ((size_t)(b * Tn + kt)) * QKV_N + Cn + h * HDn;
            #pragma unroll
            for (int itr = 0; itr < 4; itr++) {
                int f = itr * 256 + tid;
                int r = f >> 4, c = (f & 15) << 2;
                float4 kv4 = *(const float4*)(kg + (size_t)r * QKV_N + c);
                float4 tk;
                tk.x = tf32r(kv4.x); tk.y = tf32r(kv4.y);
                tk.z = tf32r(kv4.z); tk.w = tf32r(kv4.w);
                *(float4*)&Ks[r * KPAD + c] = tk;
            }
        }
        // ---- stage V as bf16 row-pair-packed hi/lo ----
        {
            const float* vg = qkv + ((size_t)(b * Tn + kt)) * QKV_N + 2 * Cn + h * HDn;
            #pragma unroll
            for (int itr = 0; itr < 2; itr++) {
                int f = itr * 256 + tid;
                int p  = f >> 4;
                int c4 = (f & 15) * 4;
                const float* r0p = vg + (size_t)(2 * p) * QKV_N + c4;
                float4 v0 = *(const float4*)r0p;
                float4 v1 = *(const float4*)(r0p + QKV_N);
                uint32_t hw[4], lw[4];
                const float e0[4] = {v0.x, v0.y, v0.z, v0.w};
                const float e1[4] = {v1.x, v1.y, v1.z, v1.w};
                #pragma unroll
                for (int j = 0; j < 4; j++) {
                    __nv_bfloat162 hp = __floats2bfloat162_rn(e0[j], e1[j]);
                    hw[j] = *(uint32_t*)&hp;
                    float2 hf = __bfloat1622float2(hp);
                    __nv_bfloat162 lp = __floats2bfloat162_rn(e0[j] - hf.x, e1[j] - hf.y);
                    lw[j] = *(uint32_t*)&lp;
                }
                *(uint4*)&Vph[p * VSTR + c4] = make_uint4(hw[0], hw[1], hw[2], hw[3]);
                *(uint4*)&Vpl[p * VSTR + c4] = make_uint4(lw[0], lw[1], lw[2], lw[3]);
            }
        }
        __syncthreads();

        if (kt <= w_qmax) {
            // ---- S = Q @ K^T (k-major, scale pre-folded into Q) ----
            float S[8][4];
            #pragma unroll
            for (int nt = 0; nt < 8; nt++) {
                S[nt][0] = S[nt][1] = S[nt][2] = S[nt][3] = 0.f;
            }
            #pragma unroll
            for (int k = 0; k < 8; k++) {
                #pragma unroll
                for (int nt = 0; nt < 8; nt++) {
                    uint32_t b0 = __float_as_uint(Ks[(nt * 8 + g) * KPAD + k * 8 + tg    ]);
                    uint32_t b1 = __float_as_uint(Ks[(nt * 8 + g) * KPAD + k * 8 + tg + 4]);
                    mma_tf32(S[nt], Aq[k], b0, b1);
                }
            }

            const bool need_mask = (kt + AT_BKV - 1 > w_qmin);
            if (need_mask) {
                #pragma unroll
                for (int nt = 0; nt < 8; nt++) {
                    int j0 = kt + nt * 8 + 2 * tg;
                    int j1 = j0 + 1;
                    if (j0 > qi0) S[nt][0] = -INFINITY;
                    if (j1 > qi0) S[nt][1] = -INFINITY;
                    if (j0 > qi1) S[nt][2] = -INFINITY;
                    if (j1 > qi1) S[nt][3] = -INFINITY;
                }
            }

            // ---- online softmax ----
            float mc0 = -INFINITY, mc1 = -INFINITY;
            #pragma unroll
            for (int nt = 0; nt < 8; nt++) {
                mc0 = fmaxf(mc0, fmaxf(S[nt][0], S[nt][1]));
                mc1 = fmaxf(mc1, fmaxf(S[nt][2], S[nt][3]));
            }
            mc0 = fmaxf(mc0, __shfl_xor_sync(0xffffffffu, mc0, 1));
            mc0 = fmaxf(mc0, __shfl_xor_sync(0xffffffffu, mc0, 2));
            mc1 = fmaxf(mc1, __shfl_xor_sync(0xffffffffu, mc1, 1));
            mc1 = fmaxf(mc1, __shfl_xor_sync(0xffffffffu, mc1, 2));

            float mn0 = fmaxf(m0, mc0);
            float mn1 = fmaxf(m1, mc1);
            float corr0 = __expf(m0 - mn0);
            float corr1 = __expf(m1 - mn1);
            m0 = mn0; m1 = mn1;

            float ps0 = 0.f, ps1 = 0.f;
            #pragma unroll
            for (int nt = 0; nt < 8; nt++) {
                S[nt][0] = __expf(S[nt][0] - mn0);
                S[nt][1] = __expf(S[nt][1] - mn0);
                S[nt][2] = __expf(S[nt][2] - mn1);
                S[nt][3] = __expf(S[nt][3] - mn1);
                ps0 += S[nt][0] + S[nt][1];
                ps1 += S[nt][2] + S[nt][3];
            }
            ps0 += __shfl_xor_sync(0xffffffffu, ps0, 1);
            ps0 += __shfl_xor_sync(0xffffffffu, ps0, 2);
            ps1 += __shfl_xor_sync(0xffffffffu, ps1, 1);
            ps1 += __shfl_xor_sync(0xffffffffu, ps1, 2);
            l0 = l0 * corr0 + ps0;
            l1 = l1 * corr1 + ps1;

            #pragma unroll
            for (int nt = 0; nt < 8; nt++) {
                O[nt][0] *= corr0; O[nt][1] *= corr0;
                O[nt][2] *= corr1; O[nt][3] *= corr1;
            }

            // ---- O += P @ V in bf16 split: C-frag P packs directly ----
            #pragma unroll
            for (int s = 0; s < 4; s++) {
                uint32_t aph[4], apl[4];
                const float pv[8] = {
                    S[2*s  ][0], S[2*s  ][1], S[2*s  ][2], S[2*s  ][3],
                    S[2*s+1][0], S[2*s+1][1], S[2*s+1][2], S[2*s+1][3]
                };
                #pragma unroll
                for (int q = 0; q < 4; q++) {
                    __nv_bfloat162 hp = __floats2bfloat162_rn(pv[2*q], pv[2*q+1]);
                    aph[q] = *(uint32_t*)&hp;
                    float2 hf = __bfloat1622float2(hp);
                    __nv_bfloat162 lp = __floats2bfloat162_rn(pv[2*q] - hf.x,
                                                              pv[2*q+1] - hf.y);
                    apl[q] = *(uint32_t*)&lp;
                }
                const int pr0 = (8 * s + tg) * VSTR;
                const int pr1 = (8 * s + tg + 4) * VSTR;
                #pragma unroll
                for (int dd = 0; dd < 8; dd++) {
                    const int dc = dd * 8 + g;
                    uint32_t b0h = Vph[pr0 + dc];
                    uint32_t b1h = Vph[pr1 + dc];
                    uint32_t b0l = Vpl[pr0 + dc];
                    uint32_t b1l = Vpl[pr1 + dc];
                    mma_bf16(O[dd], aph, b0h, b1h);
                    mma_bf16(O[dd], aph, b0l, b1l);
                    mma_bf16(O[dd], apl, b0h, b1h);
                }
            }
        }
        __syncthreads();
    }

    // ---- finalize: divide by l, split to fp16 hi/lo, store ----
    const float inv0 = 1.f / l0;
    const float inv1 = 1.f / l1;
    const size_t row0 = (size_t)(b * Tn + qi0) * Cn + h * HDn;
    const size_t row1 = (size_t)(b * Tn + qi1) * Cn + h * HDn;
    #pragma unroll
    for (int nt = 0; nt < 8; nt++) {
        int c = nt * 8 + 2 * tg;
        float v00 = O[nt][0] * inv0, v01 = O[nt][1] * inv0;
        float v10 = O[nt][2] * inv1, v11 = O[nt][3] * inv1;
        __half h00 = __float2half_rn(v00), h01 = __float2half_rn(v01);
        __half h10 = __float2half_rn(v10), h11 = __float2half_rn(v11);
        *(__half2*)&yhi[row0 + c] = __half2(h00, h01);
        *(__half2*)&yhi[row1 + c] = __half2(h10, h11);
        *(__half2*)&ylo[row0 + c] = __half2(
            __float2half_rn(v00 - __half2float(h00)),
            __float2half_rn(v01 - __half2float(h01)));
        *(__half2*)&ylo[row1 + c] = __half2(
            __float2half_rn(v10 - __half2float(h10)),
            __float2half_rn(v11 - __half2float(h11)));
    }
}

// ---------------------------------------------------------------------------
// Launch
// ---------------------------------------------------------------------------
extern "C" void kernel_launch(void* const* d_in, const int* in_sizes, int n_in,
                              void* d_out, int out_size)
{
    const float* x      = (const float*)d_in[0];
    const float* w_attn = (const float*)d_in[1];
    const float* b_attn = (const float*)d_in[2];
    const float* w_proj = (const float*)d_in[3];
    const float* b_proj = (const float*)d_in[4];
    float* out = (float*)d_out;

    float* qkv_ptr; __half *xhi, *xlo, *wah, *wph, *yhi, *ylo;
    cudaGetSymbolAddress((void**)&qkv_ptr, g_qkv);
    cudaGetSymbolAddress((void**)&xhi, g_xhi);
    cudaGetSymbolAddress((void**)&xlo, g_xlo);
    cudaGetSymbolAddress((void**)&wah, g_wah);
    cudaGetSymbolAddress((void**)&wph, g_wph);
    cudaGetSymbolAddress((void**)&yhi, g_yhi);
    cudaGetSymbolAddress((void**)&ylo, g_ylo);

    cudaFuncSetAttribute(hgemm_2p, cudaFuncAttributeMaxDynamicSharedMemorySize, GEMM_SMEM);

    // 0) split x (hi/lo fp16); convert weights to fp16
    {
        int n4;
        n4 = (Mrows * Cn) / 4;
        split2h<<<(n4 + 255) / 256, 256>>>(x, xhi, xlo, n4);
        n4 = (Cn * QKV_N) / 4;
        conv_h<<<(n4 + 255) / 256, 256>>>(w_attn, wah, n4);
        n4 = (Cn * Cn) / 4;
        conv_h<<<(n4 + 255) / 256, 256>>>(w_proj, wph, n4);
    }
    // 1) QKV projection (fp16 2-pass)
    {
        dim3 grid(QKV_N / GBN, Mrows / GBM);
        hgemm_2p<<<grid, 256, GEMM_SMEM>>>(xhi, xlo, wah, b_attn,
                                           qkv_ptr, Mrows, QKV_N, Cn);
    }
    // 2) Causal attention (R8: tf32 QK + bf16-split PV), y out as fp16 hi/lo
    {
        dim3 grid(Tn / AT_BQ, Hn, Bn);
        attn_tc<<<grid, 256>>>(qkv_ptr, yhi, ylo);
    }
    // 3) Output projection (fp16 2-pass)
    {
        dim3 grid(Cn / GBN, Mrows / GBM);
        hgemm_2p<<<grid, 256, GEMM_SMEM>>>(yhi, ylo, wph, b_proj,
                                           out, Mrows, Cn, Cn);
    }
}